// round 7
// baseline (speedup 1.0000x reference)
#include <cuda_runtime.h>
#include <cstdint>

#define B_ 32
#define I_ 1152
#define O_ 10
#define D_ 16
#define H_ 10
#define S_ 922
#define T_ 512
#define PAD 20          // s_u row stride: 80B -> conflict-free for stride access

// ---------------------------------------------------------------------------
// One block per (b,o). All intermediates in shared memory.
//  0:  dtype probe (safe), zero, load u -> s_u
//  0b: vn from s_u; vectorized idx gather -> smem atomicOr bitmask
//  1:  masked weighted accumulation -> Mu numerators (5 acc/thread)
//  1b: den pass (10 warps); Mu = num/den; mu2
//  2:  loss: thread owns full i-row (16 q regs), Mu hoisted to regs,
//      two passes of 5 h; 1 sqrt per (i,h), no shuffles in inner loop
//  argmin by warp 0 (shfl reduce), emit Mu[h*]
// ---------------------------------------------------------------------------
__global__ void __launch_bounds__(T_, 2) fused_kernel(const float* __restrict__ u,
                                                      const int* __restrict__ idx,
                                                      float* __restrict__ out) {
    extern __shared__ float sm[];
    float*    s_u    = sm;                         // [1152][PAD]
    float*    s_vn   = sm + I_ * PAD;              // [1152]
    unsigned* s_mask = (unsigned*)(s_vn + I_);     // [1152]

    __shared__ float s_MuNum[H_ * D_];
    __shared__ float s_den[H_];
    __shared__ __align__(16) float s_Mu[H_][D_];
    __shared__ float s_mu2[H_];
    __shared__ float s_loss[16][H_];
    __shared__ int   s_is64;

    const int bo   = blockIdx.x;
    const int b    = bo / O_;
    const int o    = bo % O_;
    const int tid  = threadIdx.x;
    const int lane = tid & 31;
    const int w    = tid >> 5;      // warp 0..15

    const float* ub = u + ((size_t)b * I_ * O_ + o) * D_;

    // ---- phase 0: dtype probe + zero + load u ----
    if (w == 0) {
        unsigned v = ((const unsigned*)idx)[2 * lane + 1]
                   | ((const unsigned*)idx)[2 * (lane + 32) + 1];
        unsigned r = __reduce_or_sync(0xffffffffu, v);
        if (lane == 0) s_is64 = (r == 0u) ? 1 : 0;
    }
    for (int j = tid; j < I_; j += T_) s_mask[j] = 0u;
    if (tid < H_ * D_) s_MuNum[tid] = 0.f;

    for (int e = tid; e < I_ * 4; e += T_) {
        int i = e >> 2, j = e & 3;
        float4 q = *(const float4*)(ub + (size_t)i * (O_ * D_) + j * 4);
        *(float4*)(s_u + i * PAD + j * 4) = q;
    }
    __syncthreads();

    // ---- phase 0b: norms + vectorized gather/scatter ----
    for (int i = tid; i < I_; i += T_) {
        const float4* p = (const float4*)(s_u + i * PAD);
        float4 q0 = p[0], q1 = p[1], q2 = p[2], q3 = p[3];
        float s = q0.x * q0.x + q0.y * q0.y + q0.z * q0.z + q0.w * q0.w
                + q1.x * q1.x + q1.y * q1.y + q1.z * q1.z + q1.w * q1.w
                + q2.x * q2.x + q2.y * q2.y + q2.z * q2.z + q2.w * q2.w
                + q3.x * q3.x + q3.y * q3.y + q3.z * q3.z + q3.w * q3.w;
        s_vn[i] = sqrtf(s);
    }

    if (s_is64) {
#pragma unroll 1
        for (int s = tid; s < S_; s += T_) {
            int base = ((b * S_ + s) * O_ + o) * H_;
            const int4* p = (const int4*)idx + (base >> 1);
            int4 a0 = p[0], a1 = p[1], a2 = p[2], a3 = p[3], a4 = p[4];
            atomicOr(&s_mask[a0.x], 1u << 0);
            atomicOr(&s_mask[a0.z], 1u << 1);
            atomicOr(&s_mask[a1.x], 1u << 2);
            atomicOr(&s_mask[a1.z], 1u << 3);
            atomicOr(&s_mask[a2.x], 1u << 4);
            atomicOr(&s_mask[a2.z], 1u << 5);
            atomicOr(&s_mask[a3.x], 1u << 6);
            atomicOr(&s_mask[a3.z], 1u << 7);
            atomicOr(&s_mask[a4.x], 1u << 8);
            atomicOr(&s_mask[a4.z], 1u << 9);
        }
    } else {
#pragma unroll 1
        for (int s = tid; s < S_; s += T_) {
            int base = ((b * S_ + s) * O_ + o) * H_;
            const int2* p = (const int2*)idx + (base >> 1);
            int2 a0 = p[0], a1 = p[1], a2 = p[2], a3 = p[3], a4 = p[4];
            atomicOr(&s_mask[a0.x], 1u << 0);
            atomicOr(&s_mask[a0.y], 1u << 1);
            atomicOr(&s_mask[a1.x], 1u << 2);
            atomicOr(&s_mask[a1.y], 1u << 3);
            atomicOr(&s_mask[a2.x], 1u << 4);
            atomicOr(&s_mask[a2.y], 1u << 5);
            atomicOr(&s_mask[a3.x], 1u << 6);
            atomicOr(&s_mask[a3.y], 1u << 7);
            atomicOr(&s_mask[a4.x], 1u << 8);
            atomicOr(&s_mask[a4.y], 1u << 9);
        }
    }
    __syncthreads();

    // ---- phase 1: masked accumulation (warp = i-stripe; lane halves = h-halves) ----
    {
        const int d  = lane & 15;
        const int hb = (lane >> 4) * 5;       // 0 or 5
        float a0 = 0.f, a1 = 0.f, a2 = 0.f, a3 = 0.f, a4 = 0.f;
#pragma unroll 4
        for (int i = w; i < I_; i += 16) {    // 72 iterations
            unsigned m  = s_mask[i] >> hb;
            float    t0 = s_vn[i] * s_u[i * PAD + d];
            if (m & 1u)  a0 += t0;
            if (m & 2u)  a1 += t0;
            if (m & 4u)  a2 += t0;
            if (m & 8u)  a3 += t0;
            if (m & 16u) a4 += t0;
        }
        atomicAdd(&s_MuNum[(hb + 0) * D_ + d], a0);
        atomicAdd(&s_MuNum[(hb + 1) * D_ + d], a1);
        atomicAdd(&s_MuNum[(hb + 2) * D_ + d], a2);
        atomicAdd(&s_MuNum[(hb + 3) * D_ + d], a3);
        atomicAdd(&s_MuNum[(hb + 4) * D_ + d], a4);
    }

    // ---- phase 1b: den pass (10 warps, one h each) ----
    if (w < H_) {
        unsigned bit = 1u << w;
        float dn = 0.f;
#pragma unroll 4
        for (int i = lane; i < I_; i += 32)
            if (s_mask[i] & bit) dn += s_vn[i];
#pragma unroll
        for (int off = 16; off > 0; off >>= 1)
            dn += __shfl_down_sync(0xffffffffu, dn, off);
        if (lane == 0) s_den[w] = dn;
    }
    __syncthreads();

    if (tid < H_ * D_) {
        int h = tid >> 4;
        s_Mu[h][tid & 15] = s_MuNum[tid] / s_den[h];
    }
    __syncthreads();
    if (tid < H_) {
        float m2 = 0.f;
#pragma unroll
        for (int dd = 0; dd < D_; dd++) { float x = s_Mu[tid][dd]; m2 += x * x; }
        s_mu2[tid] = m2;
    }
    __syncthreads();

    // ---- phase 2: losses, full i-row per thread, Mu in registers ----
#pragma unroll 1
    for (int pass = 0; pass < 2; pass++) {
        const int hb = pass * 5;
        float4 m0[5], m1[5], m2v[5], m3[5];
        float  u2[5];
#pragma unroll
        for (int hh = 0; hh < 5; hh++) {
            const float4* mp = (const float4*)&s_Mu[hb + hh][0];
            m0[hh] = mp[0]; m1[hh] = mp[1]; m2v[hh] = mp[2]; m3[hh] = mp[3];
            u2[hh] = s_mu2[hb + hh];
        }
        float l0 = 0.f, l1 = 0.f, l2 = 0.f, l3 = 0.f, l4 = 0.f;
#pragma unroll 1
        for (int i = tid; i < I_; i += T_) {   // 2 or 3 iterations
            const float4* p = (const float4*)(s_u + i * PAD);
            float4 q0 = p[0], q1 = p[1], q2 = p[2], q3 = p[3];
            float  v  = s_vn[i];
            float  sq = v * v;
#pragma unroll
            for (int hh = 0; hh < 5; hh++) {
                float dot = q0.x * m0[hh].x + q0.y * m0[hh].y
                          + q0.z * m0[hh].z + q0.w * m0[hh].w
                          + q1.x * m1[hh].x + q1.y * m1[hh].y
                          + q1.z * m1[hh].z + q1.w * m1[hh].w
                          + q2.x * m2v[hh].x + q2.y * m2v[hh].y
                          + q2.z * m2v[hh].z + q2.w * m2v[hh].w
                          + q3.x * m3[hh].x + q3.y * m3[hh].y
                          + q3.z * m3[hh].z + q3.w * m3[hh].w;
                float val = sqrtf(fmaxf(sq + fmaf(-2.f, dot, u2[hh]), 0.f));
                if (hh == 0) l0 += val;
                else if (hh == 1) l1 += val;
                else if (hh == 2) l2 += val;
                else if (hh == 3) l3 += val;
                else l4 += val;
            }
        }
#pragma unroll
        for (int off = 16; off > 0; off >>= 1) {
            l0 += __shfl_down_sync(0xffffffffu, l0, off);
            l1 += __shfl_down_sync(0xffffffffu, l1, off);
            l2 += __shfl_down_sync(0xffffffffu, l2, off);
            l3 += __shfl_down_sync(0xffffffffu, l3, off);
            l4 += __shfl_down_sync(0xffffffffu, l4, off);
        }
        if (lane == 0) {
            s_loss[w][hb + 0] = l0;
            s_loss[w][hb + 1] = l1;
            s_loss[w][hb + 2] = l2;
            s_loss[w][hb + 3] = l3;
            s_loss[w][hb + 4] = l4;
        }
    }
    __syncthreads();

    // ---- argmin + output: warp 0 only (shfl min-reduce) ----
    if (w == 0) {
        float myv = 3.4e38f;
        int   myh = 0;
        if (lane < H_) {
            float l = 0.f;
#pragma unroll
            for (int ww = 0; ww < 16; ww++) l += s_loss[ww][lane];
            myv = l; myh = lane;
        }
#pragma unroll
        for (int off = 16; off > 0; off >>= 1) {
            float ov = __shfl_xor_sync(0xffffffffu, myv, off);
            int   oh = __shfl_xor_sync(0xffffffffu, myh, off);
            if (ov < myv || (ov == myv && oh < myh)) { myv = ov; myh = oh; }
        }
        if (lane < D_) out[(size_t)bo * D_ + lane] = s_Mu[myh][lane];
    }
}

// ---------------------------------------------------------------------------
extern "C" void kernel_launch(void* const* d_in, const int* in_sizes, int n_in,
                              void* d_out, int out_size) {
    const float* u   = (const float*)d_in[0];
    const int*   idx = (const int*)d_in[1];
    float*       out = (float*)d_out;
    (void)in_sizes; (void)n_in; (void)out_size;

    const int dynSmem = (I_ * PAD + I_ + I_) * 4;   // 101376 bytes
    static int attr_set = 0;
    if (!attr_set) {
        cudaFuncSetAttribute(fused_kernel,
                             cudaFuncAttributeMaxDynamicSharedMemorySize, dynSmem);
        attr_set = 1;
    }
    fused_kernel<<<B_ * O_, T_, dynSmem>>>(u, idx, out);
}

// round 8
// speedup vs baseline: 1.9064x; 1.9064x over previous
#include <cuda_runtime.h>
#include <cstdint>

#define B_ 32
#define I_ 1152
#define O_ 10
#define D_ 16
#define H_ 10
#define S_ 922
#define T_ 512
#define PAD 20          // s_u row stride: 80B -> conflict-free for stride access

__device__ __forceinline__ float sqrt_approx(float x) {
    float y;
    asm("sqrt.approx.f32 %0, %1;" : "=f"(y) : "f"(x));
    return y;
}

// ---------------------------------------------------------------------------
// One block per (b,o). All intermediates in shared memory.
//  0:  dtype probe (safe), zero, load u -> s_u
//  0b: vn from s_u (approx sqrt); vectorized idx gather -> smem atomicOr mask
//  1:  masked weighted accumulation -> Mu numerators (5 acc/thread)
//  1b: den pass (10 warps); Mu = num/den; mu2
//  2:  loss: quad owns d-quarters; Mu QUARTERS hoisted to regs (20/pass),
//      two passes of 5 h; dot via 2x shfl.xor; sqrt.approx (1 instr)
//  argmin by warp 0 (shfl reduce), emit Mu[h*]
// ---------------------------------------------------------------------------
__global__ void __launch_bounds__(T_, 2) fused_kernel(const float* __restrict__ u,
                                                      const int* __restrict__ idx,
                                                      float* __restrict__ out) {
    extern __shared__ float sm[];
    float*    s_u    = sm;                         // [1152][PAD]
    float*    s_vn   = sm + I_ * PAD;              // [1152]
    unsigned* s_mask = (unsigned*)(s_vn + I_);     // [1152]

    __shared__ float s_MuNum[H_ * D_];
    __shared__ float s_den[H_];
    __shared__ __align__(16) float s_Mu[H_][D_];
    __shared__ float s_mu2[H_];
    __shared__ float s_loss[16][H_];
    __shared__ int   s_is64;

    const int bo   = blockIdx.x;
    const int b    = bo / O_;
    const int o    = bo % O_;
    const int tid  = threadIdx.x;
    const int lane = tid & 31;
    const int w    = tid >> 5;      // warp 0..15

    const float* ub = u + ((size_t)b * I_ * O_ + o) * D_;

    // ---- phase 0: dtype probe + zero + load u ----
    if (w == 0) {
        unsigned v = ((const unsigned*)idx)[2 * lane + 1]
                   | ((const unsigned*)idx)[2 * (lane + 32) + 1];
        unsigned r = __reduce_or_sync(0xffffffffu, v);
        if (lane == 0) s_is64 = (r == 0u) ? 1 : 0;
    }
    for (int j = tid; j < I_; j += T_) s_mask[j] = 0u;
    if (tid < H_ * D_) s_MuNum[tid] = 0.f;

    for (int e = tid; e < I_ * 4; e += T_) {
        int i = e >> 2, j = e & 3;
        float4 q = *(const float4*)(ub + (size_t)i * (O_ * D_) + j * 4);
        *(float4*)(s_u + i * PAD + j * 4) = q;
    }
    __syncthreads();

    // ---- phase 0b: norms + vectorized gather/scatter ----
    for (int i = tid; i < I_; i += T_) {
        const float4* p = (const float4*)(s_u + i * PAD);
        float4 q0 = p[0], q1 = p[1], q2 = p[2], q3 = p[3];
        float s = q0.x * q0.x + q0.y * q0.y + q0.z * q0.z + q0.w * q0.w
                + q1.x * q1.x + q1.y * q1.y + q1.z * q1.z + q1.w * q1.w
                + q2.x * q2.x + q2.y * q2.y + q2.z * q2.z + q2.w * q2.w
                + q3.x * q3.x + q3.y * q3.y + q3.z * q3.z + q3.w * q3.w;
        s_vn[i] = sqrt_approx(s);
    }

    if (s_is64) {
#pragma unroll 1
        for (int s = tid; s < S_; s += T_) {
            int base = ((b * S_ + s) * O_ + o) * H_;
            const int4* p = (const int4*)idx + (base >> 1);
            int4 a0 = p[0], a1 = p[1], a2 = p[2], a3 = p[3], a4 = p[4];
            atomicOr(&s_mask[a0.x], 1u << 0);
            atomicOr(&s_mask[a0.z], 1u << 1);
            atomicOr(&s_mask[a1.x], 1u << 2);
            atomicOr(&s_mask[a1.z], 1u << 3);
            atomicOr(&s_mask[a2.x], 1u << 4);
            atomicOr(&s_mask[a2.z], 1u << 5);
            atomicOr(&s_mask[a3.x], 1u << 6);
            atomicOr(&s_mask[a3.z], 1u << 7);
            atomicOr(&s_mask[a4.x], 1u << 8);
            atomicOr(&s_mask[a4.z], 1u << 9);
        }
    } else {
#pragma unroll 1
        for (int s = tid; s < S_; s += T_) {
            int base = ((b * S_ + s) * O_ + o) * H_;
            const int2* p = (const int2*)idx + (base >> 1);
            int2 a0 = p[0], a1 = p[1], a2 = p[2], a3 = p[3], a4 = p[4];
            atomicOr(&s_mask[a0.x], 1u << 0);
            atomicOr(&s_mask[a0.y], 1u << 1);
            atomicOr(&s_mask[a1.x], 1u << 2);
            atomicOr(&s_mask[a1.y], 1u << 3);
            atomicOr(&s_mask[a2.x], 1u << 4);
            atomicOr(&s_mask[a2.y], 1u << 5);
            atomicOr(&s_mask[a3.x], 1u << 6);
            atomicOr(&s_mask[a3.y], 1u << 7);
            atomicOr(&s_mask[a4.x], 1u << 8);
            atomicOr(&s_mask[a4.y], 1u << 9);
        }
    }
    __syncthreads();

    // ---- phase 1: masked accumulation (warp = i-stripe; lane halves = h-halves) ----
    {
        const int d  = lane & 15;
        const int hb = (lane >> 4) * 5;       // 0 or 5
        float a0 = 0.f, a1 = 0.f, a2 = 0.f, a3 = 0.f, a4 = 0.f;
#pragma unroll 4
        for (int i = w; i < I_; i += 16) {    // 72 iterations
            unsigned m  = s_mask[i] >> hb;
            float    t0 = s_vn[i] * s_u[i * PAD + d];
            if (m & 1u)  a0 += t0;
            if (m & 2u)  a1 += t0;
            if (m & 4u)  a2 += t0;
            if (m & 8u)  a3 += t0;
            if (m & 16u) a4 += t0;
        }
        atomicAdd(&s_MuNum[(hb + 0) * D_ + d], a0);
        atomicAdd(&s_MuNum[(hb + 1) * D_ + d], a1);
        atomicAdd(&s_MuNum[(hb + 2) * D_ + d], a2);
        atomicAdd(&s_MuNum[(hb + 3) * D_ + d], a3);
        atomicAdd(&s_MuNum[(hb + 4) * D_ + d], a4);
    }

    // ---- phase 1b: den pass (10 warps, one h each) ----
    if (w < H_) {
        unsigned bit = 1u << w;
        float dn = 0.f;
#pragma unroll 4
        for (int i = lane; i < I_; i += 32)
            if (s_mask[i] & bit) dn += s_vn[i];
#pragma unroll
        for (int off = 16; off > 0; off >>= 1)
            dn += __shfl_down_sync(0xffffffffu, dn, off);
        if (lane == 0) s_den[w] = dn;
    }
    __syncthreads();

    if (tid < H_ * D_) {
        int h = tid >> 4;
        s_Mu[h][tid & 15] = s_MuNum[tid] / s_den[h];
    }
    __syncthreads();
    if (tid < H_) {
        float m2 = 0.f;
#pragma unroll
        for (int dd = 0; dd < D_; dd++) { float x = s_Mu[tid][dd]; m2 += x * x; }
        s_mu2[tid] = m2;
    }
    __syncthreads();

    // ---- phase 2: losses; quad owns d-quarter, Mu quarters in regs ----
    {
        const int dq = tid & 3;               // d-quarter owned
        const int g  = tid >> 2;              // 0..127 (i-group)
#pragma unroll 1
        for (int pass = 0; pass < 2; pass++) {
            const int hb = pass * 5;
            float4 mq[5];
            float  u2[5];
#pragma unroll
            for (int hh = 0; hh < 5; hh++) {
                mq[hh] = *(const float4*)(&s_Mu[hb + hh][dq * 4]);
                u2[hh] = s_mu2[hb + hh];
            }
            float l0 = 0.f, l1 = 0.f, l2 = 0.f, l3 = 0.f, l4 = 0.f;
#pragma unroll 1
            for (int k = 0; k < I_ / 128; k++) {  // 9 iterations
                int i = g + k * 128;
                float4 q = *(const float4*)(s_u + i * PAD + dq * 4);
                float  v = s_vn[i];
                float sq = v * v;
#pragma unroll
                for (int hh = 0; hh < 5; hh++) {
                    float dot = q.x * mq[hh].x + q.y * mq[hh].y
                              + q.z * mq[hh].z + q.w * mq[hh].w;
                    dot += __shfl_xor_sync(0xffffffffu, dot, 1);
                    dot += __shfl_xor_sync(0xffffffffu, dot, 2);
                    float val = sqrt_approx(fmaxf(sq + fmaf(-2.f, dot, u2[hh]), 0.f));
                    if (hh == 0) l0 += val;        // x4 per i (all quad lanes)
                    else if (hh == 1) l1 += val;
                    else if (hh == 2) l2 += val;
                    else if (hh == 3) l3 += val;
                    else l4 += val;
                }
            }
            // warp reduce (totals uniformly 4x true loss -> argmin unaffected)
#pragma unroll
            for (int off = 16; off > 0; off >>= 1) {
                l0 += __shfl_down_sync(0xffffffffu, l0, off);
                l1 += __shfl_down_sync(0xffffffffu, l1, off);
                l2 += __shfl_down_sync(0xffffffffu, l2, off);
                l3 += __shfl_down_sync(0xffffffffu, l3, off);
                l4 += __shfl_down_sync(0xffffffffu, l4, off);
            }
            if (lane == 0) {
                s_loss[w][hb + 0] = l0;
                s_loss[w][hb + 1] = l1;
                s_loss[w][hb + 2] = l2;
                s_loss[w][hb + 3] = l3;
                s_loss[w][hb + 4] = l4;
            }
        }
    }
    __syncthreads();

    // ---- argmin + output: warp 0 only (shfl min-reduce) ----
    if (w == 0) {
        float myv = 3.4e38f;
        int   myh = 0;
        if (lane < H_) {
            float l = 0.f;
#pragma unroll
            for (int ww = 0; ww < 16; ww++) l += s_loss[ww][lane];
            myv = l; myh = lane;
        }
#pragma unroll
        for (int off = 16; off > 0; off >>= 1) {
            float ov = __shfl_xor_sync(0xffffffffu, myv, off);
            int   oh = __shfl_xor_sync(0xffffffffu, myh, off);
            if (ov < myv || (ov == myv && oh < myh)) { myv = ov; myh = oh; }
        }
        if (lane < D_) out[(size_t)bo * D_ + lane] = s_Mu[myh][lane];
    }
}

// ---------------------------------------------------------------------------
extern "C" void kernel_launch(void* const* d_in, const int* in_sizes, int n_in,
                              void* d_out, int out_size) {
    const float* u   = (const float*)d_in[0];
    const int*   idx = (const int*)d_in[1];
    float*       out = (float*)d_out;
    (void)in_sizes; (void)n_in; (void)out_size;

    const int dynSmem = (I_ * PAD + I_ + I_) * 4;   // 101376 bytes
    static int attr_set = 0;
    if (!attr_set) {
        cudaFuncSetAttribute(fused_kernel,
                             cudaFuncAttributeMaxDynamicSharedMemorySize, dynSmem);
        attr_set = 1;
    }
    fused_kernel<<<B_ * O_, T_, dynSmem>>>(u, idx, out);
}